// round 6
// baseline (speedup 1.0000x reference)
#include <cuda_runtime.h>

// Decoder: y_{t+1} = y_t + cutoff * tanh(dt * MLP_b(y_t) / cutoff), per-batch weights.
// 256 CTAs (one batch), 256 threads, persistent over T=1000 steps.
// Exact ReLU sparsity: skip weight rows whose input h[k]==0 (ballot compaction).
// Sparse matvec: warp-per-row-slice, 8 outputs/thread (2x LDG.128 per row covering a
// full 1KB row per warp), unroll-8 rows => 16 LDG.128 in flight per thread.
// in/out weights + biases pinned in SMEM.

#define NB 256
#define NC 16
#define NH 256
#define NT 1000
#define TB 8   // output staging depth (NT % TB == 0)

__global__ __launch_bounds__(256, 2)
void decoder_kernel(const float* __restrict__ y0,
                    const float* __restrict__ in_w,    // [B, C, H]
                    const float* __restrict__ in_b,    // [B, H]
                    const float* __restrict__ out_w,   // [B, H, C]
                    const float* __restrict__ out_b,   // [B, C]
                    const float* __restrict__ pw,      // [B, 2, H, H] (row = input k)
                    const float* __restrict__ pb,      // [B, 2, H]
                    const float* __restrict__ cutoff,  // [1]
                    float* __restrict__ out)           // [B, C, T]
{
    __shared__ float  in_s[NC * NH];     // [c][i]
    __shared__ float  out_s[NH * NC];    // [k][c]
    __shared__ float2 act[NH];           // compacted (h, row byte-offset as bits)
    __shared__ int    cnt_s[8];
    __shared__ float  ys[NC];
    __shared__ float  po8[8 * NH];       // [group 0..7][output i] partials
    __shared__ float  po_s[256];         // out-layer partials [g16][c]
    __shared__ float  stage[NC][TB];

    const int b    = blockIdx.x;
    const int i    = threadIdx.x;
    const int lane = i & 31;
    const int wid  = i >> 5;   // warp = row group 0..7

    // ---- preload per-batch small weights into SMEM ----
    const float* inwb  = in_w  + (size_t)b * NC * NH;
    const float* outwb = out_w + (size_t)b * NH * NC;

#pragma unroll
    for (int c = 0; c < NC; c++)
        in_s[c * NH + i] = inwb[c * NH + i];

#pragma unroll
    for (int q = 0; q < 4; q++) {
        float4 v = *reinterpret_cast<const float4*>(outwb + i * NC + q * 4);
        *reinterpret_cast<float4*>(&out_s[i * NC + q * 4]) = v;
    }

    const float bin = in_b[(size_t)b * NH + i];
    const float bp0 = pb[(size_t)b * 2 * NH + i];
    const float bp1 = pb[(size_t)b * 2 * NH + NH + i];
    const float ob  = (i < NC) ? out_b[(size_t)b * NC + i] : 0.f;
    const float cut = cutoff[0];
    const float dt  = 1e-6f;

    if (i < NC) ys[i] = y0[(size_t)b * NC + i];

    const char* pw0 = reinterpret_cast<const char*>(pw + (size_t)b * 2 * NH * NH);
    const char* pw1 = pw0 + (size_t)NH * NH * sizeof(float);
    float* outg = out + (size_t)b * NC * NT;

    int na = 0;  // active count (uniform across CTA after compact)

    // Deterministic compaction of nonzero h into act[] (warp-major, lane order).
    auto compact = [&](float hv) {
        bool nz = hv > 0.f;
        unsigned bal = __ballot_sync(0xffffffffu, nz);
        if (lane == 0) cnt_s[wid] = __popc(bal);
        __syncthreads();
        int base = 0, tot = 0;
#pragma unroll
        for (int w = 0; w < 8; w++) {
            int cc = cnt_s[w];
            tot += cc;
            if (w < wid) base += cc;
        }
        na = tot;
        if (nz) {
            int pos = base + __popc(bal & ((1u << lane) - 1u));
            act[pos] = make_float2(hv, __int_as_float(i << 10));  // byte off = k*H*4
        }
        __syncthreads();
    };

    // Sparse matvec, warp-per-row-slice, 8 outputs/thread:
    // thread (wid, lane) accumulates outputs [lane*8 .. lane*8+7] over rows m ≡ wid (mod 8).
    // Each row: 2x LDG.128 at (row_off + lane*32) and +16. Unroll 8 rows => 16 loads in flight.
    auto dotp8 = [&](const char* wbase, float4& a0, float4& a1) {
        const char* bo = wbase + (size_t)(lane * 32);
        a0 = make_float4(0.f, 0.f, 0.f, 0.f);
        a1 = make_float4(0.f, 0.f, 0.f, 0.f);
        int m = wid;
        for (; m + 56 < na; m += 64) {
            float2 e0 = act[m +  0], e1 = act[m +  8], e2 = act[m + 16], e3 = act[m + 24];
            float2 e4 = act[m + 32], e5 = act[m + 40], e6 = act[m + 48], e7 = act[m + 56];
            const char* p0 = bo + __float_as_int(e0.y);
            const char* p1 = bo + __float_as_int(e1.y);
            const char* p2 = bo + __float_as_int(e2.y);
            const char* p3 = bo + __float_as_int(e3.y);
            const char* p4 = bo + __float_as_int(e4.y);
            const char* p5 = bo + __float_as_int(e5.y);
            const char* p6 = bo + __float_as_int(e6.y);
            const char* p7 = bo + __float_as_int(e7.y);
            float4 wa0 = *reinterpret_cast<const float4*>(p0);
            float4 wb0 = *reinterpret_cast<const float4*>(p0 + 16);
            float4 wa1 = *reinterpret_cast<const float4*>(p1);
            float4 wb1 = *reinterpret_cast<const float4*>(p1 + 16);
            float4 wa2 = *reinterpret_cast<const float4*>(p2);
            float4 wb2 = *reinterpret_cast<const float4*>(p2 + 16);
            float4 wa3 = *reinterpret_cast<const float4*>(p3);
            float4 wb3 = *reinterpret_cast<const float4*>(p3 + 16);
            float4 wa4 = *reinterpret_cast<const float4*>(p4);
            float4 wb4 = *reinterpret_cast<const float4*>(p4 + 16);
            float4 wa5 = *reinterpret_cast<const float4*>(p5);
            float4 wb5 = *reinterpret_cast<const float4*>(p5 + 16);
            float4 wa6 = *reinterpret_cast<const float4*>(p6);
            float4 wb6 = *reinterpret_cast<const float4*>(p6 + 16);
            float4 wa7 = *reinterpret_cast<const float4*>(p7);
            float4 wb7 = *reinterpret_cast<const float4*>(p7 + 16);
            a0.x = fmaf(e0.x, wa0.x, a0.x); a0.y = fmaf(e0.x, wa0.y, a0.y);
            a0.z = fmaf(e0.x, wa0.z, a0.z); a0.w = fmaf(e0.x, wa0.w, a0.w);
            a1.x = fmaf(e0.x, wb0.x, a1.x); a1.y = fmaf(e0.x, wb0.y, a1.y);
            a1.z = fmaf(e0.x, wb0.z, a1.z); a1.w = fmaf(e0.x, wb0.w, a1.w);
            a0.x = fmaf(e1.x, wa1.x, a0.x); a0.y = fmaf(e1.x, wa1.y, a0.y);
            a0.z = fmaf(e1.x, wa1.z, a0.z); a0.w = fmaf(e1.x, wa1.w, a0.w);
            a1.x = fmaf(e1.x, wb1.x, a1.x); a1.y = fmaf(e1.x, wb1.y, a1.y);
            a1.z = fmaf(e1.x, wb1.z, a1.z); a1.w = fmaf(e1.x, wb1.w, a1.w);
            a0.x = fmaf(e2.x, wa2.x, a0.x); a0.y = fmaf(e2.x, wa2.y, a0.y);
            a0.z = fmaf(e2.x, wa2.z, a0.z); a0.w = fmaf(e2.x, wa2.w, a0.w);
            a1.x = fmaf(e2.x, wb2.x, a1.x); a1.y = fmaf(e2.x, wb2.y, a1.y);
            a1.z = fmaf(e2.x, wb2.z, a1.z); a1.w = fmaf(e2.x, wb2.w, a1.w);
            a0.x = fmaf(e3.x, wa3.x, a0.x); a0.y = fmaf(e3.x, wa3.y, a0.y);
            a0.z = fmaf(e3.x, wa3.z, a0.z); a0.w = fmaf(e3.x, wa3.w, a0.w);
            a1.x = fmaf(e3.x, wb3.x, a1.x); a1.y = fmaf(e3.x, wb3.y, a1.y);
            a1.z = fmaf(e3.x, wb3.z, a1.z); a1.w = fmaf(e3.x, wb3.w, a1.w);
            a0.x = fmaf(e4.x, wa4.x, a0.x); a0.y = fmaf(e4.x, wa4.y, a0.y);
            a0.z = fmaf(e4.x, wa4.z, a0.z); a0.w = fmaf(e4.x, wa4.w, a0.w);
            a1.x = fmaf(e4.x, wb4.x, a1.x); a1.y = fmaf(e4.x, wb4.y, a1.y);
            a1.z = fmaf(e4.x, wb4.z, a1.z); a1.w = fmaf(e4.x, wb4.w, a1.w);
            a0.x = fmaf(e5.x, wa5.x, a0.x); a0.y = fmaf(e5.x, wa5.y, a0.y);
            a0.z = fmaf(e5.x, wa5.z, a0.z); a0.w = fmaf(e5.x, wa5.w, a0.w);
            a1.x = fmaf(e5.x, wb5.x, a1.x); a1.y = fmaf(e5.x, wb5.y, a1.y);
            a1.z = fmaf(e5.x, wb5.z, a1.z); a1.w = fmaf(e5.x, wb5.w, a1.w);
            a0.x = fmaf(e6.x, wa6.x, a0.x); a0.y = fmaf(e6.x, wa6.y, a0.y);
            a0.z = fmaf(e6.x, wa6.z, a0.z); a0.w = fmaf(e6.x, wa6.w, a0.w);
            a1.x = fmaf(e6.x, wb6.x, a1.x); a1.y = fmaf(e6.x, wb6.y, a1.y);
            a1.z = fmaf(e6.x, wb6.z, a1.z); a1.w = fmaf(e6.x, wb6.w, a1.w);
            a0.x = fmaf(e7.x, wa7.x, a0.x); a0.y = fmaf(e7.x, wa7.y, a0.y);
            a0.z = fmaf(e7.x, wa7.z, a0.z); a0.w = fmaf(e7.x, wa7.w, a0.w);
            a1.x = fmaf(e7.x, wb7.x, a1.x); a1.y = fmaf(e7.x, wb7.y, a1.y);
            a1.z = fmaf(e7.x, wb7.z, a1.z); a1.w = fmaf(e7.x, wb7.w, a1.w);
        }
        for (; m < na; m += 8) {
            float2 e = act[m];
            const char* p = bo + __float_as_int(e.y);
            float4 wa = *reinterpret_cast<const float4*>(p);
            float4 wb = *reinterpret_cast<const float4*>(p + 16);
            a0.x = fmaf(e.x, wa.x, a0.x); a0.y = fmaf(e.x, wa.y, a0.y);
            a0.z = fmaf(e.x, wa.z, a0.z); a0.w = fmaf(e.x, wa.w, a0.w);
            a1.x = fmaf(e.x, wb.x, a1.x); a1.y = fmaf(e.x, wb.y, a1.y);
            a1.z = fmaf(e.x, wb.z, a1.z); a1.w = fmaf(e.x, wb.w, a1.w);
        }
    };

    // Dense prop layer: dotp8 -> float4 smem writes -> 8-way cross-group reduce -> relu -> compact
    auto prop_layer = [&](const char* wbase, float bias) {
        float4 a0, a1;
        dotp8(wbase, a0, a1);
        float* dst = &po8[wid * NH + lane * 8];
        *reinterpret_cast<float4*>(dst)     = a0;
        *reinterpret_cast<float4*>(dst + 4) = a1;
        __syncthreads();
        float h = bias;
#pragma unroll
        for (int g = 0; g < 8; g++) h += po8[g * NH + i];
        compact(fmaxf(h, 0.f));
    };

    __syncthreads();

    for (int t = 0; t < NT; t++) {
        // ---- input layer (all SMEM) ----
        float acc = bin;
#pragma unroll
        for (int c = 0; c < NC; c++)
            acc = fmaf(ys[c], in_s[c * NH + i], acc);
        compact(fmaxf(acc, 0.f));

        // ---- two prop layers (sparse gmem rows, float4) ----
        prop_layer(pw0, bp0);
        prop_layer(pw1, bp1);

        // ---- output layer (SMEM, sparse over k) ----
        {
            int c = i & 15, g16 = i >> 4;
            float p = 0.f;
            for (int m = g16; m < na; m += 16) {
                float2 e = act[m];
                // byte off = k<<10 -> out_s index k*16 + c = (off>>6) + c
                p = fmaf(e.x, out_s[(__float_as_int(e.y) >> 6) + c], p);
            }
            po_s[i] = p;
        }
        __syncthreads();

        if (i < NC) {
            float f = ob;
#pragma unroll
            for (int g16 = 0; g16 < 16; g16++) f += po_s[g16 * 16 + i];
            float yn = ys[i] + cut * tanhf(dt * f / cut);
            ys[i] = yn;
            stage[i][t & (TB - 1)] = yn;
        }
        __syncthreads();

        // coalesced flush every TB steps
        if ((t & (TB - 1)) == (TB - 1) && i < NC * TB) {
            int c = i >> 3, u = i & 7;
            outg[c * NT + (t - (TB - 1)) + u] = stage[c][u];
        }
    }
}

extern "C" void kernel_launch(void* const* d_in, const int* in_sizes, int n_in,
                              void* d_out, int out_size)
{
    (void)in_sizes; (void)n_in; (void)out_size;
    decoder_kernel<<<NB, 256>>>(
        (const float*)d_in[0],   // y0
        (const float*)d_in[1],   // in_weight
        (const float*)d_in[2],   // in_bias
        (const float*)d_in[3],   // out_weight
        (const float*)d_in[4],   // out_bias
        (const float*)d_in[5],   // prop_weight
        (const float*)d_in[6],   // prop_bias
        (const float*)d_in[7],   // cutoff
        (float*)d_out);
}

// round 7
// speedup vs baseline: 1.2584x; 1.2584x over previous
#include <cuda_runtime.h>

// Decoder: y_{t+1} = y_t + cutoff * tanh(dt * MLP_b(y_t) / cutoff), per-batch weights.
// 256 CTAs (one batch), 256 threads, persistent over T=1000 steps.
// Exact ReLU sparsity: skip weight rows whose input h[k]==0 (ballot compaction).
// Sparse matvec: warp w handles rows m ≡ w (mod 8); each thread owns 8 outputs as two
// CONTIGUOUS float4 segments (lane*16 and 512+lane*16) so each LDG.128 warp access is
// a fully-utilized 512B contiguous block (4 full 128B wavefronts). Unroll 8 rows =>
// 16 LDG.128 in flight per thread. in/out weights + biases pinned in SMEM.

#define NB 256
#define NC 16
#define NH 256
#define NT 1000
#define TB 8   // output staging depth (NT % TB == 0)

__global__ __launch_bounds__(256, 2)
void decoder_kernel(const float* __restrict__ y0,
                    const float* __restrict__ in_w,    // [B, C, H]
                    const float* __restrict__ in_b,    // [B, H]
                    const float* __restrict__ out_w,   // [B, H, C]
                    const float* __restrict__ out_b,   // [B, C]
                    const float* __restrict__ pw,      // [B, 2, H, H] (row = input k)
                    const float* __restrict__ pb,      // [B, 2, H]
                    const float* __restrict__ cutoff,  // [1]
                    float* __restrict__ out)           // [B, C, T]
{
    __shared__ float  in_s[NC * NH];     // [c][i]
    __shared__ float  out_s[NH * NC];    // [k][c]
    __shared__ float2 act[NH];           // compacted (h, row byte-offset as bits)
    __shared__ int    cnt_s[8];
    __shared__ float  ys[NC];
    __shared__ float  po8[8 * NH];       // [group 0..7][output i] partials
    __shared__ float  po_s[256];         // out-layer partials [g16][c]
    __shared__ float  stage[NC][TB];

    const int b    = blockIdx.x;
    const int i    = threadIdx.x;
    const int lane = i & 31;
    const int wid  = i >> 5;   // warp = row group 0..7

    // ---- preload per-batch small weights into SMEM ----
    const float* inwb  = in_w  + (size_t)b * NC * NH;
    const float* outwb = out_w + (size_t)b * NH * NC;

#pragma unroll
    for (int c = 0; c < NC; c++)
        in_s[c * NH + i] = inwb[c * NH + i];

#pragma unroll
    for (int q = 0; q < 4; q++) {
        float4 v = *reinterpret_cast<const float4*>(outwb + i * NC + q * 4);
        *reinterpret_cast<float4*>(&out_s[i * NC + q * 4]) = v;
    }

    const float bin = in_b[(size_t)b * NH + i];
    const float bp0 = pb[(size_t)b * 2 * NH + i];
    const float bp1 = pb[(size_t)b * 2 * NH + NH + i];
    const float ob  = (i < NC) ? out_b[(size_t)b * NC + i] : 0.f;
    const float cut = cutoff[0];
    const float dt  = 1e-6f;

    if (i < NC) ys[i] = y0[(size_t)b * NC + i];

    const char* pw0 = reinterpret_cast<const char*>(pw + (size_t)b * 2 * NH * NH);
    const char* pw1 = pw0 + (size_t)NH * NH * sizeof(float);
    float* outg = out + (size_t)b * NC * NT;

    int na = 0;  // active count (uniform across CTA after compact)

    // Deterministic compaction of nonzero h into act[] (warp-major, lane order).
    auto compact = [&](float hv) {
        bool nz = hv > 0.f;
        unsigned bal = __ballot_sync(0xffffffffu, nz);
        if (lane == 0) cnt_s[wid] = __popc(bal);
        __syncthreads();
        int base = 0, tot = 0;
#pragma unroll
        for (int w = 0; w < 8; w++) {
            int cc = cnt_s[w];
            tot += cc;
            if (w < wid) base += cc;
        }
        na = tot;
        if (nz) {
            int pos = base + __popc(bal & ((1u << lane) - 1u));
            act[pos] = make_float2(hv, __int_as_float(i << 10));  // byte off = k*H*4
        }
        __syncthreads();
    };

    // Sparse matvec, 8 outputs/thread, contiguous segments:
    // thread (wid, lane) accumulates outputs [lane*4..+3] (a0) and [128+lane*4..+3] (a1)
    // over rows m ≡ wid (mod 8). Per row one address: p = row + lane*16; LDG [p], [p+512].
    // Warp access = two fully-utilized 512B contiguous blocks. Unroll 8 rows.
    auto dotp8 = [&](const char* wbase, float4& a0, float4& a1) {
        const char* bo = wbase + (size_t)(lane * 16);
        a0 = make_float4(0.f, 0.f, 0.f, 0.f);
        a1 = make_float4(0.f, 0.f, 0.f, 0.f);
        int m = wid;
        for (; m + 56 < na; m += 64) {
            float2 e0 = act[m +  0], e1 = act[m +  8], e2 = act[m + 16], e3 = act[m + 24];
            float2 e4 = act[m + 32], e5 = act[m + 40], e6 = act[m + 48], e7 = act[m + 56];
            const char* p0 = bo + __float_as_int(e0.y);
            const char* p1 = bo + __float_as_int(e1.y);
            const char* p2 = bo + __float_as_int(e2.y);
            const char* p3 = bo + __float_as_int(e3.y);
            const char* p4 = bo + __float_as_int(e4.y);
            const char* p5 = bo + __float_as_int(e5.y);
            const char* p6 = bo + __float_as_int(e6.y);
            const char* p7 = bo + __float_as_int(e7.y);
            float4 wa0 = *reinterpret_cast<const float4*>(p0);
            float4 wb0 = *reinterpret_cast<const float4*>(p0 + 512);
            float4 wa1 = *reinterpret_cast<const float4*>(p1);
            float4 wb1 = *reinterpret_cast<const float4*>(p1 + 512);
            float4 wa2 = *reinterpret_cast<const float4*>(p2);
            float4 wb2 = *reinterpret_cast<const float4*>(p2 + 512);
            float4 wa3 = *reinterpret_cast<const float4*>(p3);
            float4 wb3 = *reinterpret_cast<const float4*>(p3 + 512);
            float4 wa4 = *reinterpret_cast<const float4*>(p4);
            float4 wb4 = *reinterpret_cast<const float4*>(p4 + 512);
            float4 wa5 = *reinterpret_cast<const float4*>(p5);
            float4 wb5 = *reinterpret_cast<const float4*>(p5 + 512);
            float4 wa6 = *reinterpret_cast<const float4*>(p6);
            float4 wb6 = *reinterpret_cast<const float4*>(p6 + 512);
            float4 wa7 = *reinterpret_cast<const float4*>(p7);
            float4 wb7 = *reinterpret_cast<const float4*>(p7 + 512);
            a0.x = fmaf(e0.x, wa0.x, a0.x); a0.y = fmaf(e0.x, wa0.y, a0.y);
            a0.z = fmaf(e0.x, wa0.z, a0.z); a0.w = fmaf(e0.x, wa0.w, a0.w);
            a1.x = fmaf(e0.x, wb0.x, a1.x); a1.y = fmaf(e0.x, wb0.y, a1.y);
            a1.z = fmaf(e0.x, wb0.z, a1.z); a1.w = fmaf(e0.x, wb0.w, a1.w);
            a0.x = fmaf(e1.x, wa1.x, a0.x); a0.y = fmaf(e1.x, wa1.y, a0.y);
            a0.z = fmaf(e1.x, wa1.z, a0.z); a0.w = fmaf(e1.x, wa1.w, a0.w);
            a1.x = fmaf(e1.x, wb1.x, a1.x); a1.y = fmaf(e1.x, wb1.y, a1.y);
            a1.z = fmaf(e1.x, wb1.z, a1.z); a1.w = fmaf(e1.x, wb1.w, a1.w);
            a0.x = fmaf(e2.x, wa2.x, a0.x); a0.y = fmaf(e2.x, wa2.y, a0.y);
            a0.z = fmaf(e2.x, wa2.z, a0.z); a0.w = fmaf(e2.x, wa2.w, a0.w);
            a1.x = fmaf(e2.x, wb2.x, a1.x); a1.y = fmaf(e2.x, wb2.y, a1.y);
            a1.z = fmaf(e2.x, wb2.z, a1.z); a1.w = fmaf(e2.x, wb2.w, a1.w);
            a0.x = fmaf(e3.x, wa3.x, a0.x); a0.y = fmaf(e3.x, wa3.y, a0.y);
            a0.z = fmaf(e3.x, wa3.z, a0.z); a0.w = fmaf(e3.x, wa3.w, a0.w);
            a1.x = fmaf(e3.x, wb3.x, a1.x); a1.y = fmaf(e3.x, wb3.y, a1.y);
            a1.z = fmaf(e3.x, wb3.z, a1.z); a1.w = fmaf(e3.x, wb3.w, a1.w);
            a0.x = fmaf(e4.x, wa4.x, a0.x); a0.y = fmaf(e4.x, wa4.y, a0.y);
            a0.z = fmaf(e4.x, wa4.z, a0.z); a0.w = fmaf(e4.x, wa4.w, a0.w);
            a1.x = fmaf(e4.x, wb4.x, a1.x); a1.y = fmaf(e4.x, wb4.y, a1.y);
            a1.z = fmaf(e4.x, wb4.z, a1.z); a1.w = fmaf(e4.x, wb4.w, a1.w);
            a0.x = fmaf(e5.x, wa5.x, a0.x); a0.y = fmaf(e5.x, wa5.y, a0.y);
            a0.z = fmaf(e5.x, wa5.z, a0.z); a0.w = fmaf(e5.x, wa5.w, a0.w);
            a1.x = fmaf(e5.x, wb5.x, a1.x); a1.y = fmaf(e5.x, wb5.y, a1.y);
            a1.z = fmaf(e5.x, wb5.z, a1.z); a1.w = fmaf(e5.x, wb5.w, a1.w);
            a0.x = fmaf(e6.x, wa6.x, a0.x); a0.y = fmaf(e6.x, wa6.y, a0.y);
            a0.z = fmaf(e6.x, wa6.z, a0.z); a0.w = fmaf(e6.x, wa6.w, a0.w);
            a1.x = fmaf(e6.x, wb6.x, a1.x); a1.y = fmaf(e6.x, wb6.y, a1.y);
            a1.z = fmaf(e6.x, wb6.z, a1.z); a1.w = fmaf(e6.x, wb6.w, a1.w);
            a0.x = fmaf(e7.x, wa7.x, a0.x); a0.y = fmaf(e7.x, wa7.y, a0.y);
            a0.z = fmaf(e7.x, wa7.z, a0.z); a0.w = fmaf(e7.x, wa7.w, a0.w);
            a1.x = fmaf(e7.x, wb7.x, a1.x); a1.y = fmaf(e7.x, wb7.y, a1.y);
            a1.z = fmaf(e7.x, wb7.z, a1.z); a1.w = fmaf(e7.x, wb7.w, a1.w);
        }
        for (; m < na; m += 8) {
            float2 e = act[m];
            const char* p = bo + __float_as_int(e.y);
            float4 wa = *reinterpret_cast<const float4*>(p);
            float4 wb = *reinterpret_cast<const float4*>(p + 512);
            a0.x = fmaf(e.x, wa.x, a0.x); a0.y = fmaf(e.x, wa.y, a0.y);
            a0.z = fmaf(e.x, wa.z, a0.z); a0.w = fmaf(e.x, wa.w, a0.w);
            a1.x = fmaf(e.x, wb.x, a1.x); a1.y = fmaf(e.x, wb.y, a1.y);
            a1.z = fmaf(e.x, wb.z, a1.z); a1.w = fmaf(e.x, wb.w, a1.w);
        }
    };

    // Dense prop layer: dotp8 -> two float4 smem writes -> 8-way reduce -> relu -> compact
    auto prop_layer = [&](const char* wbase, float bias) {
        float4 a0, a1;
        dotp8(wbase, a0, a1);
        float* dst = &po8[wid * NH + lane * 4];
        *reinterpret_cast<float4*>(dst)       = a0;   // outputs lane*4..+3
        *reinterpret_cast<float4*>(dst + 128) = a1;   // outputs 128+lane*4..+3
        __syncthreads();
        float h = bias;
#pragma unroll
        for (int g = 0; g < 8; g++) h += po8[g * NH + i];
        compact(fmaxf(h, 0.f));
    };

    __syncthreads();

    for (int t = 0; t < NT; t++) {
        // ---- input layer (all SMEM) ----
        float acc = bin;
#pragma unroll
        for (int c = 0; c < NC; c++)
            acc = fmaf(ys[c], in_s[c * NH + i], acc);
        compact(fmaxf(acc, 0.f));

        // ---- two prop layers (sparse gmem rows, float4) ----
        prop_layer(pw0, bp0);
        prop_layer(pw1, bp1);

        // ---- output layer (SMEM, sparse over k) ----
        {
            int c = i & 15, g16 = i >> 4;
            float p = 0.f;
            for (int m = g16; m < na; m += 16) {
                float2 e = act[m];
                // byte off = k<<10 -> out_s index k*16 + c = (off>>6) + c
                p = fmaf(e.x, out_s[(__float_as_int(e.y) >> 6) + c], p);
            }
            po_s[i] = p;
        }
        __syncthreads();

        if (i < NC) {
            float f = ob;
#pragma unroll
            for (int g16 = 0; g16 < 16; g16++) f += po_s[g16 * 16 + i];
            float yn = ys[i] + cut * tanhf(dt * f / cut);
            ys[i] = yn;
            stage[i][t & (TB - 1)] = yn;
        }
        __syncthreads();

        // coalesced flush every TB steps
        if ((t & (TB - 1)) == (TB - 1) && i < NC * TB) {
            int c = i >> 3, u = i & 7;
            outg[c * NT + (t - (TB - 1)) + u] = stage[c][u];
        }
    }
}

extern "C" void kernel_launch(void* const* d_in, const int* in_sizes, int n_in,
                              void* d_out, int out_size)
{
    (void)in_sizes; (void)n_in; (void)out_size;
    decoder_kernel<<<NB, 256>>>(
        (const float*)d_in[0],   // y0
        (const float*)d_in[1],   // in_weight
        (const float*)d_in[2],   // in_bias
        (const float*)d_in[3],   // out_weight
        (const float*)d_in[4],   // out_bias
        (const float*)d_in[5],   // prop_weight
        (const float*)d_in[6],   // prop_bias
        (const float*)d_in[7],   // cutoff
        (float*)d_out);
}